// round 4
// baseline (speedup 1.0000x reference)
#include <cuda_runtime.h>
#include <math.h>
#include <stdint.h>

#define NT 16384      // nodes
#define NE 64         // embed dim
#define NF 92         // node feature dim
#define NHID 128      // readout hidden
#define NG 64         // graphs

// ---------------- scratch (static device globals; no allocations) ------------
__device__ float  g_Xa[NT * NE];       // X buffers (ping)
__device__ float  g_Xb[NT * NE];       // X buffers (pong)
__device__ float  g_H[NT * NE];        // H = X @ W
__device__ double g_psum[128 * NE];    // per-block column partial sums (double)
__device__ double g_psq[128 * NE];     // per-block column partial sums of squares
__device__ double g_pool[NG * NE];     // raw segment sums (double)
__device__ int    g_cnt[NG];           // segment counts

// ---------------- small dense GEMM: Y[NT,64] = X[NT,K] @ W[K,64] (+bias) -----
__device__ __forceinline__ void dense_body(const float* __restrict__ X, int K,
                                           const float* __restrict__ W,
                                           const float* __restrict__ bias,
                                           float* __restrict__ Y) {
    __shared__ float sW[NF * NE];   // max K = 92
    __shared__ float sX[32 * NF];
    int tid = threadIdx.x;
    for (int idx = tid; idx < K * NE; idx += 256) sW[idx] = W[idx];
    int row0 = blockIdx.x * 32;
    for (int idx = tid; idx < 32 * K; idx += 256)
        sX[idx] = X[(size_t)row0 * K + idx];
    __syncthreads();

    int j = tid & 63;       // column
    int ry = tid >> 6;      // 0..3
    float acc[8];
#pragma unroll
    for (int i = 0; i < 8; i++) acc[i] = 0.f;
    for (int k = 0; k < K; k++) {
        float w = sW[k * NE + j];
#pragma unroll
        for (int i = 0; i < 8; i++)
            acc[i] += sX[(ry + 4 * i) * K + k] * w;
    }
    float bb = bias ? bias[j] : 0.f;
#pragma unroll
    for (int i = 0; i < 8; i++)
        Y[(size_t)(row0 + ry + 4 * i) * NE + j] = acc[i] + bb;
}

__global__ void __launch_bounds__(256) k_embed(const float* __restrict__ X,
                                               const float* __restrict__ We,
                                               const float* __restrict__ be) {
    dense_body(X, NF, We, be, g_Xa);
}
__global__ void __launch_bounds__(256) k_h1(const float* __restrict__ W1) {
    dense_body(g_Xa, NE, W1, nullptr, g_H);
}
__global__ void __launch_bounds__(256) k_h2(const float* __restrict__ W2) {
    dense_body(g_Xb, NE, W2, nullptr, g_H);
}

// ---------------- SpMM: Xn = Xc + leaky_relu(A @ H + b) ----------------------
// 64 rows per block, full 64 cols, K tiles of 64, register-prefetch double
// buffer. Two-level accumulation (per-tile partials) to keep fp32 rounding
// error small against the mean-dominated sums.
__device__ __forceinline__ void spmm_body(const float* __restrict__ A,
                                          const float* __restrict__ H,
                                          const float* __restrict__ Xc,
                                          const float* __restrict__ b,
                                          float* __restrict__ Xn) {
    __shared__ float As[64][68];   // padded to kill store conflicts
    __shared__ float Hs[64][64];
    int tid = threadIdx.x;
    int tc = tid & 15;     // col group: cols 4*tc .. 4*tc+3
    int tr = tid >> 4;     // row group: rows 4*tr .. 4*tr+3
    int lr = tid >> 4;     // loader row-in-quarter 0..15
    int lf = tid & 15;     // loader float4 index 0..15
    int row0 = blockIdx.x * 64;
    const float* Abase = A + (size_t)row0 * NT;

    float acc[4][4];
#pragma unroll
    for (int i = 0; i < 4; i++)
#pragma unroll
        for (int j = 0; j < 4; j++) acc[i][j] = 0.f;

    float4 ra[4], rh[4];
    // preload tile 0
#pragma unroll
    for (int i = 0; i < 4; i++) {
        int r = lr + 16 * i;
        ra[i] = *(const float4*)(Abase + (size_t)r * NT + lf * 4);
        rh[i] = *(const float4*)(H + (size_t)r * NE + lf * 4);
    }

    const int NKT = NT / 64;
    for (int kt = 0; kt < NKT; kt++) {
#pragma unroll
        for (int i = 0; i < 4; i++) {
            int r = lr + 16 * i;
            *(float4*)&As[r][lf * 4] = ra[i];
            *(float4*)&Hs[r][lf * 4] = rh[i];
        }
        __syncthreads();
        if (kt + 1 < NKT) {
            int kb = (kt + 1) * 64;
#pragma unroll
            for (int i = 0; i < 4; i++) {
                int r = lr + 16 * i;
                ra[i] = *(const float4*)(Abase + (size_t)r * NT + kb + lf * 4);
                rh[i] = *(const float4*)(H + (size_t)(kb + r) * NE + lf * 4);
            }
        }
        float tacc[4][4];
#pragma unroll
        for (int i = 0; i < 4; i++)
#pragma unroll
            for (int j = 0; j < 4; j++) tacc[i][j] = 0.f;
#pragma unroll 8
        for (int k = 0; k < 64; k++) {
            float4 hv = *(const float4*)&Hs[k][tc * 4];
#pragma unroll
            for (int i = 0; i < 4; i++) {
                float a = As[tr * 4 + i][k];
                tacc[i][0] += a * hv.x;
                tacc[i][1] += a * hv.y;
                tacc[i][2] += a * hv.z;
                tacc[i][3] += a * hv.w;
            }
        }
#pragma unroll
        for (int i = 0; i < 4; i++)
#pragma unroll
            for (int j = 0; j < 4; j++) acc[i][j] += tacc[i][j];
        __syncthreads();
    }

#pragma unroll
    for (int i = 0; i < 4; i++) {
        int r = row0 + tr * 4 + i;
#pragma unroll
        for (int j = 0; j < 4; j++) {
            int c = tc * 4 + j;
            float y = acc[i][j] + b[c];
            y = (y > 0.f) ? y : 0.01f * y;
            Xn[(size_t)r * NE + c] = Xc[(size_t)r * NE + c] + y;
        }
    }
}

__global__ void __launch_bounds__(256) k_spmm1(const float* __restrict__ A,
                                               const float* __restrict__ b1) {
    spmm_body(A, g_H, g_Xa, b1, g_Xb);
}
__global__ void __launch_bounds__(256) k_spmm2(const float* __restrict__ A,
                                               const float* __restrict__ b2) {
    spmm_body(A, g_H, g_Xb, b2, g_Xa);
}

// ---------------- column stats partials (double accumulators) ----------------
__global__ void __launch_bounds__(256) k_colstats() {
    int tid = threadIdx.x;
    int c = tid & 63, q = tid >> 6;
    int base = blockIdx.x * 128;
    double s = 0.0, s2 = 0.0;
    for (int i = 0; i < 32; i++) {
        double v = (double)g_Xa[(size_t)(base + q * 32 + i) * NE + c];
        s += v;
        s2 += v * v;
    }
    __shared__ double sm[256], sm2[256];
    sm[tid] = s;
    sm2[tid] = s2;
    __syncthreads();
    if (q == 0) {
        g_psum[blockIdx.x * NE + c] = sm[c] + sm[64 + c] + sm[128 + c] + sm[192 + c];
        g_psq[blockIdx.x * NE + c]  = sm2[c] + sm2[64 + c] + sm2[128 + c] + sm2[192 + c];
    }
}

// ---------------- segment sums via binary search on sorted N -----------------
__global__ void __launch_bounds__(256) k_segpool(const int* __restrict__ Nidx) {
    int g = blockIdx.x;
    int lo, hi;
    {
        int a = 0, b2 = NT;
        while (a < b2) { int m = (a + b2) >> 1; if (Nidx[m] < g) a = m + 1; else b2 = m; }
        lo = a;
    }
    {
        int a = 0, b2 = NT;
        while (a < b2) { int m = (a + b2) >> 1; if (Nidx[m] < g + 1) a = m + 1; else b2 = m; }
        hi = a;
    }
    int tid = threadIdx.x;
    int c = tid & 63, q = tid >> 6;
    double s = 0.0;
    for (int r = lo + q; r < hi; r += 4) s += (double)g_Xa[(size_t)r * NE + c];
    __shared__ double sm[256];
    sm[tid] = s;
    __syncthreads();
    if (q == 0)
        g_pool[g * NE + c] = sm[c] + sm[64 + c] + sm[128 + c] + sm[192 + c];
    if (tid == 0) g_cnt[g] = hi - lo;
}

// ---------------- finalize: BN affine on pooled + readout MLP ----------------
__global__ void __launch_bounds__(256) k_final(const float* __restrict__ gamma,
                                               const float* __restrict__ beta,
                                               const float* __restrict__ Wn1,
                                               const float* __restrict__ bn1,
                                               const float* __restrict__ Wn2,
                                               const float* __restrict__ bn2,
                                               float* __restrict__ out) {
    __shared__ float P[NG][NE];
    __shared__ float red[256];
    __shared__ double dmean[NE], dscale[NE], dbeta[NE];
    int tid = threadIdx.x;
    if (tid < NE) {
        int c = tid;
        double s = 0.0, s2 = 0.0;
        for (int b = 0; b < 128; b++) {
            s += g_psum[b * NE + c];
            s2 += g_psq[b * NE + c];
        }
        double mean = s / (double)NT;
        double var = s2 / (double)NT - mean * mean;   // safe in double
        dmean[c] = mean;
        dscale[c] = (double)gamma[c] / sqrt(var + 1e-5);
        dbeta[c] = (double)beta[c];
    }
    __syncthreads();
    // BN is affine per column and pooling is a per-column mean:
    //   pooled_bn = (pool_mean - mean) * gamma/sqrt(var+eps) + beta
    // computed in double to avoid the large-magnitude cancellation.
    for (int idx = tid; idx < NG * NE; idx += 256) {
        int g = idx >> 6, c = idx & 63;
        double ct = (double)(g_cnt[g] > 1 ? g_cnt[g] : 1);
        double pm = g_pool[idx] / ct;
        P[g][c] = (float)((pm - dmean[c]) * dscale[c] + dbeta[c]);
    }
    __syncthreads();
    int g = tid >> 2, jq = tid & 3;
    float part = 0.f;
    for (int j = jq; j < NHID; j += 4) {
        float a = bn1[j];
        for (int c = 0; c < NE; c++) a += P[g][c] * Wn1[c * NHID + j];
        part += fmaxf(a, 0.f) * Wn2[j];
    }
    red[tid] = part;
    __syncthreads();
    if (jq == 0)
        out[g] = red[tid] + red[tid + 1] + red[tid + 2] + red[tid + 3] + bn2[0];
}

// ---------------- launcher ---------------------------------------------------
extern "C" void kernel_launch(void* const* d_in, const int* in_sizes, int n_in,
                              void* d_out, int out_size) {
    const float* X    = (const float*)d_in[0];
    const float* A    = (const float*)d_in[1];
    // d_in[2] = E (unused), d_in[3] = E_avg (unused)
    const int*   Nidx = (const int*)d_in[4];
    const float* We   = (const float*)d_in[5];
    const float* be   = (const float*)d_in[6];
    const float* W1   = (const float*)d_in[7];
    const float* b1   = (const float*)d_in[8];
    const float* W2   = (const float*)d_in[9];
    const float* b2   = (const float*)d_in[10];
    const float* gam  = (const float*)d_in[11];
    const float* bet  = (const float*)d_in[12];
    const float* Wn1  = (const float*)d_in[13];
    const float* bn1  = (const float*)d_in[14];
    const float* Wn2  = (const float*)d_in[15];
    const float* bn2  = (const float*)d_in[16];
    float* out = (float*)d_out;

    k_embed<<<NT / 32, 256>>>(X, We, be);
    k_h1<<<NT / 32, 256>>>(W1);
    k_spmm1<<<NT / 64, 256>>>(A, b1);
    k_h2<<<NT / 32, 256>>>(W2);
    k_spmm2<<<NT / 64, 256>>>(A, b2);
    k_colstats<<<128, 256>>>();
    k_segpool<<<NG, 256>>>(Nidx);
    k_final<<<1, 256>>>(gam, bet, Wn1, bn1, Wn2, bn2, out);
}

// round 10
// speedup vs baseline: 1.2883x; 1.2883x over previous
#include <cuda_runtime.h>
#include <math.h>
#include <stdint.h>

#define NT 16384      // nodes
#define NE 64         // embed dim
#define NF 92         // node feature dim
#define NHID 128      // readout hidden
#define NG 64         // graphs
#define MT 128        // SpMM M tile (rows per CTA)
#define KC 32         // SpMM K chunk (2 x k16 sub-steps)
#define NCH (NT / KC) // 512 chunks

// ---------------- scratch (static device globals; no allocations) ------------
__device__ float    g_Xa[NT * NE];
__device__ float    g_Xb[NT * NE];
__device__ float    g_H[NT * NE];
// B fragments for mma.m16n8k16 (col-major B = H[k][n]), bf16 hi/lo packed x2.
// Layout: idx = (((kc16*8 + nt)*32 + lane)*2 + r); per thread reg pair adjacent.
#define NBFRAG ((NT / 16) * 8 * 32 * 2)   // 524288 u32 = 2MB each
__device__ uint32_t g_Bh[NBFRAG];
__device__ uint32_t g_Bl[NBFRAG];
__device__ double   g_psum[128 * NE];
__device__ double   g_psq[128 * NE];
__device__ double   g_pool[NG * NE];
__device__ int      g_cnt[NG];

// ---------------- bf16 split helpers -----------------------------------------
// hi = round-to-nearest bf16 of x (as float bits); lo = x - hi (exact), then
// lo itself rounded to bf16. Packed as bf16x2 (low half = first element).
__device__ __forceinline__ uint32_t bf16_hi_u(uint32_t u) {
    return (u + 0x8000u) & 0xFFFF0000u;
}
__device__ __forceinline__ uint32_t pack_hi(float2 v, float2* lo) {
    uint32_t ux = __float_as_uint(v.x), uy = __float_as_uint(v.y);
    uint32_t hx = bf16_hi_u(ux), hy = bf16_hi_u(uy);
    lo->x = v.x - __uint_as_float(hx);
    lo->y = v.y - __uint_as_float(hy);
    return (hx >> 16) | hy;
}
__device__ __forceinline__ uint32_t pack_bf2(float2 v) {
    uint32_t ux = __float_as_uint(v.x), uy = __float_as_uint(v.y);
    return (bf16_hi_u(ux) >> 16) | bf16_hi_u(uy);
}

__device__ __forceinline__ void mma_bf16(float* d, const uint32_t* a,
                                         uint32_t b0, uint32_t b1) {
    asm volatile(
        "mma.sync.aligned.m16n8k16.row.col.f32.bf16.bf16.f32 "
        "{%0,%1,%2,%3}, {%4,%5,%6,%7}, {%8,%9}, {%0,%1,%2,%3};"
        : "+f"(d[0]), "+f"(d[1]), "+f"(d[2]), "+f"(d[3])
        : "r"(a[0]), "r"(a[1]), "r"(a[2]), "r"(a[3]), "r"(b0), "r"(b1));
}

// ---------------- small dense GEMM: Y[NT,64] = X[NT,K] @ W[K,64] (+bias) -----
__device__ __forceinline__ void dense_body(const float* __restrict__ X, int K,
                                           const float* __restrict__ W,
                                           const float* __restrict__ bias,
                                           float* __restrict__ Y) {
    __shared__ float sW[NF * NE];
    __shared__ float sX[32 * NF];
    int tid = threadIdx.x;
    for (int idx = tid; idx < K * NE; idx += 256) sW[idx] = W[idx];
    int row0 = blockIdx.x * 32;
    for (int idx = tid; idx < 32 * K; idx += 256)
        sX[idx] = X[(size_t)row0 * K + idx];
    __syncthreads();

    int j = tid & 63;
    int ry = tid >> 6;
    float acc[8];
#pragma unroll
    for (int i = 0; i < 8; i++) acc[i] = 0.f;
    for (int k = 0; k < K; k++) {
        float w = sW[k * NE + j];
#pragma unroll
        for (int i = 0; i < 8; i++)
            acc[i] += sX[(ry + 4 * i) * K + k] * w;
    }
    float bb = bias ? bias[j] : 0.f;
#pragma unroll
    for (int i = 0; i < 8; i++)
        Y[(size_t)(row0 + ry + 4 * i) * NE + j] = acc[i] + bb;
}

__global__ void __launch_bounds__(256) k_embed(const float* __restrict__ X,
                                               const float* __restrict__ We,
                                               const float* __restrict__ be) {
    dense_body(X, NF, We, be, g_Xa);
}
__global__ void __launch_bounds__(256) k_h1(const float* __restrict__ W1) {
    dense_body(g_Xa, NE, W1, nullptr, g_H);
}
__global__ void __launch_bounds__(256) k_h2(const float* __restrict__ W2) {
    dense_body(g_Xb, NE, W2, nullptr, g_H);
}

// ---------------- build B fragments from H -----------------------------------
// One thread per u32 slot. idx = (((kc*8 + nt)*32 + lane)*2 + r)
__global__ void __launch_bounds__(256) k_bsplit() {
    int idx = blockIdx.x * 256 + threadIdx.x;
    int r = idx & 1;
    int lane = (idx >> 1) & 31;
    int nt = (idx >> 6) & 7;
    int kc = idx >> 9;
    int k0 = kc * 16 + (lane & 3) * 2 + r * 8;
    int n = nt * 8 + (lane >> 2);
    float2 v = make_float2(g_H[(size_t)k0 * NE + n], g_H[(size_t)(k0 + 1) * NE + n]);
    float2 lo;
    g_Bh[idx] = pack_hi(v, &lo);
    g_Bl[idx] = pack_bf2(lo);
}

// ---------------- tensor-core SpMM: Xn = Xc + leaky_relu(A@H + b) ------------
// bf16 2-term split, 3 products, fp32 accumulation via mma.sync.m16n8k16.
__device__ __forceinline__ void spmm_mma(const float* __restrict__ A,
                                         const float* __restrict__ bias,
                                         const float* __restrict__ Xc,
                                         float* __restrict__ Xn) {
    // per KC=32 chunk: 2 sub-chunks x 8 ntiles x 32 lanes x 2 regs = 1024 u32
    __shared__ __align__(16) uint32_t sBh[2][1024];
    __shared__ __align__(16) uint32_t sBl[2][1024];

    int tid = threadIdx.x, wid = tid >> 5, lane = tid & 31;
    int row0 = blockIdx.x * MT + wid * 16;
    int r_a = lane >> 2;          // row in 16-row strip (and +8)
    int c_a = (lane & 3) * 2;     // k offset within k16 (and +8)

    const float* A0 = A + (size_t)(row0 + r_a) * NT + c_a;
    const float* A1 = A + (size_t)(row0 + r_a + 8) * NT + c_a;

    float acc[8][4];
#pragma unroll
    for (int nt = 0; nt < 8; nt++)
#pragma unroll
        for (int i = 0; i < 4; i++) acc[nt][i] = 0.f;

    // prologue: B chunk 0 -> stage 0, A chunk 0 -> regs
    {
        const uint4* srcH = (const uint4*)g_Bh;
        const uint4* srcL = (const uint4*)g_Bl;
        ((uint4*)sBh[0])[tid] = srcH[tid];
        ((uint4*)sBl[0])[tid] = srcL[tid];
    }
    float2 araw[8];
#pragma unroll
    for (int s = 0; s < 2; s++) {
        int kb = s * 16;
        araw[s * 4 + 0] = *(const float2*)(A0 + kb);
        araw[s * 4 + 1] = *(const float2*)(A1 + kb);
        araw[s * 4 + 2] = *(const float2*)(A0 + kb + 8);
        araw[s * 4 + 3] = *(const float2*)(A1 + kb + 8);
    }
    __syncthreads();

#pragma unroll 1
    for (int ch = 0; ch < NCH; ch++) {
        int st = ch & 1;
        // stage next B chunk into the other buffer
        if (ch + 1 < NCH) {
            const uint4* srcH = (const uint4*)(g_Bh + (ch + 1) * 1024);
            const uint4* srcL = (const uint4*)(g_Bl + (ch + 1) * 1024);
            ((uint4*)sBh[st ^ 1])[tid] = srcH[tid];
            ((uint4*)sBl[st ^ 1])[tid] = srcL[tid];
        }
        // split current A into hi/lo bf16x2 fragments
        uint32_t ah[8], al[8];
#pragma unroll
        for (int i = 0; i < 8; i++) {
            float2 lo;
            ah[i] = pack_hi(araw[i], &lo);
            al[i] = pack_bf2(lo);
        }
        // prefetch next A chunk
        if (ch + 1 < NCH) {
            int kb0 = (ch + 1) * KC;
#pragma unroll
            for (int s = 0; s < 2; s++) {
                int kb = kb0 + s * 16;
                araw[s * 4 + 0] = *(const float2*)(A0 + kb);
                araw[s * 4 + 1] = *(const float2*)(A1 + kb);
                araw[s * 4 + 2] = *(const float2*)(A0 + kb + 8);
                araw[s * 4 + 3] = *(const float2*)(A1 + kb + 8);
            }
        }
        // compute: 2 sub-chunks x 8 ntiles x 3 products
#pragma unroll
        for (int s = 0; s < 2; s++) {
#pragma unroll
            for (int nt = 0; nt < 8; nt++) {
                int off = (s * 8 + nt) * 64 + lane * 2;
                uint2 bh = *(const uint2*)&sBh[st][off];
                uint2 bl = *(const uint2*)&sBl[st][off];
                mma_bf16(acc[nt], &ah[s * 4], bh.x, bh.y);
                mma_bf16(acc[nt], &ah[s * 4], bl.x, bl.y);
                mma_bf16(acc[nt], &al[s * 4], bh.x, bh.y);
            }
        }
        __syncthreads();
    }

    // epilogue: bias + leaky_relu + residual
    int r1 = row0 + r_a, r2 = r1 + 8;
#pragma unroll
    for (int nt = 0; nt < 8; nt++) {
        int cc = nt * 8 + c_a;
        float b0 = bias[cc], b1 = bias[cc + 1];
        float2 x1 = *(const float2*)(Xc + (size_t)r1 * NE + cc);
        float2 x2 = *(const float2*)(Xc + (size_t)r2 * NE + cc);
        float y0 = acc[nt][0] + b0; y0 = (y0 > 0.f) ? y0 : 0.01f * y0;
        float y1 = acc[nt][1] + b1; y1 = (y1 > 0.f) ? y1 : 0.01f * y1;
        float y2 = acc[nt][2] + b0; y2 = (y2 > 0.f) ? y2 : 0.01f * y2;
        float y3 = acc[nt][3] + b1; y3 = (y3 > 0.f) ? y3 : 0.01f * y3;
        *(float2*)(Xn + (size_t)r1 * NE + cc) = make_float2(x1.x + y0, x1.y + y1);
        *(float2*)(Xn + (size_t)r2 * NE + cc) = make_float2(x2.x + y2, x2.y + y3);
    }
}

__global__ void __launch_bounds__(256) k_spmm1(const float* __restrict__ A,
                                               const float* __restrict__ b1) {
    spmm_mma(A, b1, g_Xa, g_Xb);
}
__global__ void __launch_bounds__(256) k_spmm2(const float* __restrict__ A,
                                               const float* __restrict__ b2) {
    spmm_mma(A, b2, g_Xb, g_Xa);
}

// ---------------- column stats partials (double accumulators) ----------------
__global__ void __launch_bounds__(256) k_colstats() {
    int tid = threadIdx.x;
    int c = tid & 63, q = tid >> 6;
    int base = blockIdx.x * 128;
    double s = 0.0, s2 = 0.0;
    for (int i = 0; i < 32; i++) {
        double v = (double)g_Xa[(size_t)(base + q * 32 + i) * NE + c];
        s += v;
        s2 += v * v;
    }
    __shared__ double sm[256], sm2[256];
    sm[tid] = s;
    sm2[tid] = s2;
    __syncthreads();
    if (q == 0) {
        g_psum[blockIdx.x * NE + c] = sm[c] + sm[64 + c] + sm[128 + c] + sm[192 + c];
        g_psq[blockIdx.x * NE + c]  = sm2[c] + sm2[64 + c] + sm2[128 + c] + sm2[192 + c];
    }
}

// ---------------- segment sums via binary search on sorted N -----------------
__global__ void __launch_bounds__(256) k_segpool(const int* __restrict__ Nidx) {
    int g = blockIdx.x;
    int lo, hi;
    {
        int a = 0, b2 = NT;
        while (a < b2) { int m = (a + b2) >> 1; if (Nidx[m] < g) a = m + 1; else b2 = m; }
        lo = a;
    }
    {
        int a = 0, b2 = NT;
        while (a < b2) { int m = (a + b2) >> 1; if (Nidx[m] < g + 1) a = m + 1; else b2 = m; }
        hi = a;
    }
    int tid = threadIdx.x;
    int c = tid & 63, q = tid >> 6;
    double s = 0.0;
    for (int r = lo + q; r < hi; r += 4) s += (double)g_Xa[(size_t)r * NE + c];
    __shared__ double sm[256];
    sm[tid] = s;
    __syncthreads();
    if (q == 0)
        g_pool[g * NE + c] = sm[c] + sm[64 + c] + sm[128 + c] + sm[192 + c];
    if (tid == 0) g_cnt[g] = hi - lo;
}

// ---------------- finalize: BN affine on pooled + readout MLP ----------------
__global__ void __launch_bounds__(256) k_final(const float* __restrict__ gamma,
                                               const float* __restrict__ beta,
                                               const float* __restrict__ Wn1,
                                               const float* __restrict__ bn1,
                                               const float* __restrict__ Wn2,
                                               const float* __restrict__ bn2,
                                               float* __restrict__ out) {
    __shared__ float P[NG][NE];
    __shared__ float red[256];
    __shared__ double dmean[NE], dscale[NE], dbeta[NE];
    int tid = threadIdx.x;
    if (tid < NE) {
        int c = tid;
        double s = 0.0, s2 = 0.0;
        for (int b = 0; b < 128; b++) {
            s += g_psum[b * NE + c];
            s2 += g_psq[b * NE + c];
        }
        double mean = s / (double)NT;
        double var = s2 / (double)NT - mean * mean;
        dmean[c] = mean;
        dscale[c] = (double)gamma[c] / sqrt(var + 1e-5);
        dbeta[c] = (double)beta[c];
    }
    __syncthreads();
    for (int idx = tid; idx < NG * NE; idx += 256) {
        int g = idx >> 6, c = idx & 63;
        double ct = (double)(g_cnt[g] > 1 ? g_cnt[g] : 1);
        double pm = g_pool[idx] / ct;
        P[g][c] = (float)((pm - dmean[c]) * dscale[c] + dbeta[c]);
    }
    __syncthreads();
    int g = tid >> 2, jq = tid & 3;
    float part = 0.f;
    for (int j = jq; j < NHID; j += 4) {
        float a = bn1[j];
        for (int c = 0; c < NE; c++) a += P[g][c] * Wn1[c * NHID + j];
        part += fmaxf(a, 0.f) * Wn2[j];
    }
    red[tid] = part;
    __syncthreads();
    if (jq == 0)
        out[g] = red[tid] + red[tid + 1] + red[tid + 2] + red[tid + 3] + bn2[0];
}

// ---------------- launcher ---------------------------------------------------
extern "C" void kernel_launch(void* const* d_in, const int* in_sizes, int n_in,
                              void* d_out, int out_size) {
    const float* X    = (const float*)d_in[0];
    const float* A    = (const float*)d_in[1];
    const int*   Nidx = (const int*)d_in[4];
    const float* We   = (const float*)d_in[5];
    const float* be   = (const float*)d_in[6];
    const float* W1   = (const float*)d_in[7];
    const float* b1   = (const float*)d_in[8];
    const float* W2   = (const float*)d_in[9];
    const float* b2   = (const float*)d_in[10];
    const float* gam  = (const float*)d_in[11];
    const float* bet  = (const float*)d_in[12];
    const float* Wn1  = (const float*)d_in[13];
    const float* bn1  = (const float*)d_in[14];
    const float* Wn2  = (const float*)d_in[15];
    const float* bn2  = (const float*)d_in[16];
    float* out = (float*)d_out;

    k_embed<<<NT / 32, 256>>>(X, We, be);
    k_h1<<<NT / 32, 256>>>(W1);
    k_bsplit<<<NBFRAG / 256, 256>>>();
    k_spmm1<<<NT / MT, 256>>>(A, b1);
    k_h2<<<NT / 32, 256>>>(W2);
    k_bsplit<<<NBFRAG / 256, 256>>>();
    k_spmm2<<<NT / MT, 256>>>(A, b2);
    k_colstats<<<128, 256>>>();
    k_segpool<<<NG, 256>>>(Nidx);
    k_final<<<1, 256>>>(gam, bet, Wn1, bn1, Wn2, bn2, out);
}

// round 14
// speedup vs baseline: 1.6821x; 1.3057x over previous
#include <cuda_runtime.h>
#include <math.h>
#include <stdint.h>

#define NT 16384      // nodes
#define NE 64         // embed dim
#define NF 92         // node feature dim
#define NHID 128      // readout hidden
#define NG 64         // graphs
#define MT 64         // SpMM M tile (rows per CTA) -> grid 256
#define KC 32         // SpMM K chunk (2 x k16 sub-steps)
#define NCH (NT / KC) // 512 chunks

// ---------------- scratch (static device globals; no allocations) ------------
__device__ float    g_Xa[NT * NE];
__device__ float    g_Xb[NT * NE];
__device__ float    g_H[NT * NE];
// B fragments for mma.m16n8k16 (col-major B = H[k][n]), bf16 hi/lo packed x2.
// Layout: idx = (((kc16*8 + nt)*32 + lane)*2 + r)
#define NBFRAG ((NT / 16) * 8 * 32 * 2)
__device__ uint32_t g_Bh[NBFRAG];
__device__ uint32_t g_Bl[NBFRAG];
__device__ double   g_psum[128 * NE];
__device__ double   g_psq[128 * NE];
__device__ double   g_pool[NG * NE];
__device__ int      g_cnt[NG];

// ---------------- helpers ----------------------------------------------------
__device__ __forceinline__ uint32_t bf16_hi_u(uint32_t u) {
    return (u + 0x8000u) & 0xFFFF0000u;
}
__device__ __forceinline__ uint32_t pack_hi(float2 v, float2* lo) {
    uint32_t ux = __float_as_uint(v.x), uy = __float_as_uint(v.y);
    uint32_t hx = bf16_hi_u(ux), hy = bf16_hi_u(uy);
    lo->x = v.x - __uint_as_float(hx);
    lo->y = v.y - __uint_as_float(hy);
    return (hx >> 16) | hy;
}
__device__ __forceinline__ uint32_t pack_bf2(float2 v) {
    uint32_t ux = __float_as_uint(v.x), uy = __float_as_uint(v.y);
    return (bf16_hi_u(ux) >> 16) | bf16_hi_u(uy);
}
__device__ __forceinline__ void mma_bf16(float* d, const uint32_t* a,
                                         uint32_t b0, uint32_t b1) {
    asm volatile(
        "mma.sync.aligned.m16n8k16.row.col.f32.bf16.bf16.f32 "
        "{%0,%1,%2,%3}, {%4,%5,%6,%7}, {%8,%9}, {%0,%1,%2,%3};"
        : "+f"(d[0]), "+f"(d[1]), "+f"(d[2]), "+f"(d[3])
        : "r"(a[0]), "r"(a[1]), "r"(a[2]), "r"(a[3]), "r"(b0), "r"(b1));
}

// ---------------- small dense GEMM: Y[NT,64] = X[NT,K] @ W[K,64] (+bias) -----
__device__ __forceinline__ void dense_body(const float* __restrict__ X, int K,
                                           const float* __restrict__ W,
                                           const float* __restrict__ bias,
                                           float* __restrict__ Y) {
    __shared__ float sW[NF * NE];
    __shared__ float sX[32 * NF];
    int tid = threadIdx.x;
    for (int idx = tid; idx < K * NE; idx += 256) sW[idx] = W[idx];
    int row0 = blockIdx.x * 32;
    for (int idx = tid; idx < 32 * K; idx += 256)
        sX[idx] = X[(size_t)row0 * K + idx];
    __syncthreads();

    int j = tid & 63;
    int ry = tid >> 6;
    float acc[8];
#pragma unroll
    for (int i = 0; i < 8; i++) acc[i] = 0.f;
    for (int k = 0; k < K; k++) {
        float w = sW[k * NE + j];
#pragma unroll
        for (int i = 0; i < 8; i++)
            acc[i] += sX[(ry + 4 * i) * K + k] * w;
    }
    float bb = bias ? bias[j] : 0.f;
#pragma unroll
    for (int i = 0; i < 8; i++)
        Y[(size_t)(row0 + ry + 4 * i) * NE + j] = acc[i] + bb;
}

__global__ void __launch_bounds__(256) k_embed(const float* __restrict__ X,
                                               const float* __restrict__ We,
                                               const float* __restrict__ be) {
    dense_body(X, NF, We, be, g_Xa);
}
__global__ void __launch_bounds__(256) k_h1(const float* __restrict__ W1) {
    dense_body(g_Xa, NE, W1, nullptr, g_H);
}
__global__ void __launch_bounds__(256) k_h2(const float* __restrict__ W2) {
    dense_body(g_Xb, NE, W2, nullptr, g_H);
}

// ---------------- build B fragments from H -----------------------------------
__global__ void __launch_bounds__(256) k_bsplit() {
    int idx = blockIdx.x * 256 + threadIdx.x;
    int r = idx & 1;
    int lane = (idx >> 1) & 31;
    int nt = (idx >> 6) & 7;
    int kc = idx >> 9;
    int k0 = kc * 16 + (lane & 3) * 2 + r * 8;
    int n = nt * 8 + (lane >> 2);
    float2 v = make_float2(g_H[(size_t)k0 * NE + n], g_H[(size_t)(k0 + 1) * NE + n]);
    float2 lo;
    g_Bh[idx] = pack_hi(v, &lo);
    g_Bl[idx] = pack_bf2(lo);
}

// ---------------- tensor-core SpMM: Xn = Xc + leaky_relu(A@H + b) ------------
// bf16 2-term split, 3 products, fp32 accumulation via mma.sync.m16n8k16.
// R10-proven two-buffer staging (LDG->STS, barrier after compute).
// New tiling: MT=64 rows/CTA, 8 warps = 4 row-strips x 2 col-halves.
__device__ __forceinline__ void spmm_mma(const float* __restrict__ A,
                                         const float* __restrict__ bias,
                                         const float* __restrict__ Xc,
                                         float* __restrict__ Xn) {
    // per KC=32 chunk: 2 sub-chunks x 8 ntiles x 32 lanes x 2 regs = 1024 u32
    __shared__ __align__(16) uint32_t sBh[2][1024];
    __shared__ __align__(16) uint32_t sBl[2][1024];

    int tid = threadIdx.x, wid = tid >> 5, lane = tid & 31;
    int rowgrp = wid >> 1;        // 0..3 (16-row strip)
    int colh = wid & 1;           // 0..1 (32-col half)
    int row0 = blockIdx.x * MT + rowgrp * 16;
    int r_a = lane >> 2;          // row in strip (and +8)
    int c_a = (lane & 3) * 2;     // k offset within k16 (and +8)

    const float* A0 = A + (size_t)(row0 + r_a) * NT + c_a;
    const float* A1 = A + (size_t)(row0 + r_a + 8) * NT + c_a;

    float acc[4][4];
#pragma unroll
    for (int nt = 0; nt < 4; nt++)
#pragma unroll
        for (int i = 0; i < 4; i++) acc[nt][i] = 0.f;

    // prologue: B chunk 0 -> stage 0, A chunk 0 -> regs
    {
        const uint4* srcH = (const uint4*)g_Bh;
        const uint4* srcL = (const uint4*)g_Bl;
        ((uint4*)sBh[0])[tid] = srcH[tid];
        ((uint4*)sBl[0])[tid] = srcL[tid];
    }
    float2 araw[8];
#pragma unroll
    for (int s = 0; s < 2; s++) {
        int kb = s * 16;
        araw[s * 4 + 0] = *(const float2*)(A0 + kb);
        araw[s * 4 + 1] = *(const float2*)(A1 + kb);
        araw[s * 4 + 2] = *(const float2*)(A0 + kb + 8);
        araw[s * 4 + 3] = *(const float2*)(A1 + kb + 8);
    }
    __syncthreads();

#pragma unroll 1
    for (int ch = 0; ch < NCH; ch++) {
        int st = ch & 1;
        // stage next B chunk into the other buffer
        if (ch + 1 < NCH) {
            const uint4* srcH = (const uint4*)(g_Bh + (ch + 1) * 1024);
            const uint4* srcL = (const uint4*)(g_Bl + (ch + 1) * 1024);
            ((uint4*)sBh[st ^ 1])[tid] = srcH[tid];
            ((uint4*)sBl[st ^ 1])[tid] = srcL[tid];
        }
        // split current A into hi/lo bf16x2 fragments
        uint32_t ah[8], al[8];
#pragma unroll
        for (int i = 0; i < 8; i++) {
            float2 lo;
            ah[i] = pack_hi(araw[i], &lo);
            al[i] = pack_bf2(lo);
        }
        // prefetch next A chunk
        if (ch + 1 < NCH) {
            int kb0 = (ch + 1) * KC;
#pragma unroll
            for (int s = 0; s < 2; s++) {
                int kb = kb0 + s * 16;
                araw[s * 4 + 0] = *(const float2*)(A0 + kb);
                araw[s * 4 + 1] = *(const float2*)(A1 + kb);
                araw[s * 4 + 2] = *(const float2*)(A0 + kb + 8);
                araw[s * 4 + 3] = *(const float2*)(A1 + kb + 8);
            }
        }
        // compute: 2 sub-chunks x 4 ntiles (this col half) x 3 products
#pragma unroll
        for (int s = 0; s < 2; s++) {
#pragma unroll
            for (int nt = 0; nt < 4; nt++) {
                int gnt = colh * 4 + nt;
                int off = (s * 8 + gnt) * 64 + lane * 2;
                uint2 bh = *(const uint2*)&sBh[st][off];
                uint2 bl = *(const uint2*)&sBl[st][off];
                mma_bf16(acc[nt], &ah[s * 4], bh.x, bh.y);
                mma_bf16(acc[nt], &ah[s * 4], bl.x, bl.y);
                mma_bf16(acc[nt], &al[s * 4], bh.x, bh.y);
            }
        }
        __syncthreads();
    }

    // epilogue: bias + leaky_relu + residual
    int r1 = row0 + r_a, r2 = r1 + 8;
#pragma unroll
    for (int nt = 0; nt < 4; nt++) {
        int cc = (colh * 4 + nt) * 8 + c_a;
        float b0 = bias[cc], b1 = bias[cc + 1];
        float2 x1 = *(const float2*)(Xc + (size_t)r1 * NE + cc);
        float2 x2 = *(const float2*)(Xc + (size_t)r2 * NE + cc);
        float y0 = acc[nt][0] + b0; y0 = (y0 > 0.f) ? y0 : 0.01f * y0;
        float y1 = acc[nt][1] + b1; y1 = (y1 > 0.f) ? y1 : 0.01f * y1;
        float y2 = acc[nt][2] + b0; y2 = (y2 > 0.f) ? y2 : 0.01f * y2;
        float y3 = acc[nt][3] + b1; y3 = (y3 > 0.f) ? y3 : 0.01f * y3;
        *(float2*)(Xn + (size_t)r1 * NE + cc) = make_float2(x1.x + y0, x1.y + y1);
        *(float2*)(Xn + (size_t)r2 * NE + cc) = make_float2(x2.x + y2, x2.y + y3);
    }
}

__global__ void __launch_bounds__(256, 2) k_spmm1(const float* __restrict__ A,
                                                  const float* __restrict__ b1) {
    spmm_mma(A, b1, g_Xa, g_Xb);
}
__global__ void __launch_bounds__(256, 2) k_spmm2(const float* __restrict__ A,
                                                  const float* __restrict__ b2) {
    spmm_mma(A, b2, g_Xb, g_Xa);
}

// ---------------- column stats partials (double accumulators) ----------------
__global__ void __launch_bounds__(256) k_colstats() {
    int tid = threadIdx.x;
    int c = tid & 63, q = tid >> 6;
    int base = blockIdx.x * 128;
    double s = 0.0, s2 = 0.0;
    for (int i = 0; i < 32; i++) {
        double v = (double)g_Xa[(size_t)(base + q * 32 + i) * NE + c];
        s += v;
        s2 += v * v;
    }
    __shared__ double sm[256], sm2[256];
    sm[tid] = s;
    sm2[tid] = s2;
    __syncthreads();
    if (q == 0) {
        g_psum[blockIdx.x * NE + c] = sm[c] + sm[64 + c] + sm[128 + c] + sm[192 + c];
        g_psq[blockIdx.x * NE + c]  = sm2[c] + sm2[64 + c] + sm2[128 + c] + sm2[192 + c];
    }
}

// ---------------- segment sums via binary search on sorted N -----------------
__global__ void __launch_bounds__(256) k_segpool(const int* __restrict__ Nidx) {
    int g = blockIdx.x;
    int lo, hi;
    {
        int a = 0, b2 = NT;
        while (a < b2) { int m = (a + b2) >> 1; if (Nidx[m] < g) a = m + 1; else b2 = m; }
        lo = a;
    }
    {
        int a = 0, b2 = NT;
        while (a < b2) { int m = (a + b2) >> 1; if (Nidx[m] < g + 1) a = m + 1; else b2 = m; }
        hi = a;
    }
    int tid = threadIdx.x;
    int c = tid & 63, q = tid >> 6;
    double s = 0.0;
    for (int r = lo + q; r < hi; r += 4) s += (double)g_Xa[(size_t)r * NE + c];
    __shared__ double sm[256];
    sm[tid] = s;
    __syncthreads();
    if (q == 0)
        g_pool[g * NE + c] = sm[c] + sm[64 + c] + sm[128 + c] + sm[192 + c];
    if (tid == 0) g_cnt[g] = hi - lo;
}

// ---------------- finalize: BN affine on pooled + readout MLP ----------------
__global__ void __launch_bounds__(256) k_final(const float* __restrict__ gamma,
                                               const float* __restrict__ beta,
                                               const float* __restrict__ Wn1,
                                               const float* __restrict__ bn1,
                                               const float* __restrict__ Wn2,
                                               const float* __restrict__ bn2,
                                               float* __restrict__ out) {
    __shared__ float P[NG][NE];
    __shared__ float red[256];
    __shared__ double dmean[NE], dscale[NE], dbeta[NE];
    int tid = threadIdx.x;
    if (tid < NE) {
        int c = tid;
        double s = 0.0, s2 = 0.0;
        for (int b = 0; b < 128; b++) {
            s += g_psum[b * NE + c];
            s2 += g_psq[b * NE + c];
        }
        double mean = s / (double)NT;
        double var = s2 / (double)NT - mean * mean;
        dmean[c] = mean;
        dscale[c] = (double)gamma[c] / sqrt(var + 1e-5);
        dbeta[c] = (double)beta[c];
    }
    __syncthreads();
    for (int idx = tid; idx < NG * NE; idx += 256) {
        int g = idx >> 6, c = idx & 63;
        double ct = (double)(g_cnt[g] > 1 ? g_cnt[g] : 1);
        double pm = g_pool[idx] / ct;
        P[g][c] = (float)((pm - dmean[c]) * dscale[c] + dbeta[c]);
    }
    __syncthreads();
    int g = tid >> 2, jq = tid & 3;
    float part = 0.f;
    for (int j = jq; j < NHID; j += 4) {
        float a = bn1[j];
        for (int c = 0; c < NE; c++) a += P[g][c] * Wn1[c * NHID + j];
        part += fmaxf(a, 0.f) * Wn2[j];
    }
    red[tid] = part;
    __syncthreads();
    if (jq == 0)
        out[g] = red[tid] + red[tid + 1] + red[tid + 2] + red[tid + 3] + bn2[0];
}

// ---------------- launcher ---------------------------------------------------
extern "C" void kernel_launch(void* const* d_in, const int* in_sizes, int n_in,
                              void* d_out, int out_size) {
    const float* X    = (const float*)d_in[0];
    const float* A    = (const float*)d_in[1];
    const int*   Nidx = (const int*)d_in[4];
    const float* We   = (const float*)d_in[5];
    const float* be   = (const float*)d_in[6];
    const float* W1   = (const float*)d_in[7];
    const float* b1   = (const float*)d_in[8];
    const float* W2   = (const float*)d_in[9];
    const float* b2   = (const float*)d_in[10];
    const float* gam  = (const float*)d_in[11];
    const float* bet  = (const float*)d_in[12];
    const float* Wn1  = (const float*)d_in[13];
    const float* bn1  = (const float*)d_in[14];
    const float* Wn2  = (const float*)d_in[15];
    const float* bn2  = (const float*)d_in[16];
    float* out = (float*)d_out;

    k_embed<<<NT / 32, 256>>>(X, We, be);
    k_h1<<<NT / 32, 256>>>(W1);
    k_bsplit<<<NBFRAG / 256, 256>>>();
    k_spmm1<<<NT / MT, 256>>>(A, b1);
    k_h2<<<NT / 32, 256>>>(W2);
    k_bsplit<<<NBFRAG / 256, 256>>>();
    k_spmm2<<<NT / MT, 256>>>(A, b2);
    k_colstats<<<128, 256>>>();
    k_segpool<<<NG, 256>>>(Nidx);
    k_final<<<1, 256>>>(gam, bet, Wn1, bn1, Wn2, bn2, out);
}